// round 1
// baseline (speedup 1.0000x reference)
#include <cuda_runtime.h>
#include <cuda_bf16.h>

// CRF loss: out[b] = logZ(b) - gold_score(b)
// B=2048 sequences, L=512 max steps, T=32 states.
// One warp per batch element; lane j owns state j.
// Forward recurrence in "prob space": with M = exp(transition),
//   alpha'[j] = e[j] + m + log( sum_i exp(d[i]-m) * M[i][j] )
// which is 1 exp + 32-wide mat-vec (shfl broadcast + FFMA) + 1 log per step.
// Early exit at l == length[b] (mask is a prefix).

#define CRF_B 2048
#define CRF_L 512
#define CRF_T 32

__global__ __launch_bounds__(256, 8)
void crf_forward_kernel(const float* __restrict__ emit,      // (B, L, T)
                        const float* __restrict__ trans,     // (T, T)
                        const int*   __restrict__ tags,      // (B, L)
                        const int*   __restrict__ lengths,   // (B,)
                        float*       __restrict__ out)       // (B,)
{
    const unsigned FULL = 0xffffffffu;
    int gwarp = (blockIdx.x * blockDim.x + threadIdx.x) >> 5;
    int lane  = threadIdx.x & 31;
    if (gwarp >= CRF_B) return;
    const int b   = gwarp;
    const int len = lengths[b];

    // Column j of M = exp(transition): Mcol[i] = exp(trans[i][j]).
    // Across lanes, each load i is a contiguous 128B row -> coalesced.
    float Mcol[CRF_T];
#pragma unroll
    for (int i = 0; i < CRF_T; i++)
        Mcol[i] = __expf(__ldg(&trans[i * CRF_T + lane]));

    const float* erow = emit + (size_t)b * CRF_L * CRF_T;

    // alpha_0 = emit[b, 0, :]
    float d = __ldg(&erow[lane]);

    for (int l = 1; l < len; l++) {
        float e = __ldg(&erow[l * CRF_T + lane]);   // coalesced 128B per warp
        // Normalize by lane 0's value (cheap; ratios are well-bounded in fp32)
        float m = __shfl_sync(FULL, d, 0);
        float p = __expf(d - m);
        float a0 = 0.f, a1 = 0.f, a2 = 0.f, a3 = 0.f;
#pragma unroll
        for (int i = 0; i < CRF_T; i += 4) {
            a0 = fmaf(__shfl_sync(FULL, p, i + 0), Mcol[i + 0], a0);
            a1 = fmaf(__shfl_sync(FULL, p, i + 1), Mcol[i + 1], a1);
            a2 = fmaf(__shfl_sync(FULL, p, i + 2), Mcol[i + 2], a2);
            a3 = fmaf(__shfl_sync(FULL, p, i + 3), Mcol[i + 3], a3);
        }
        d = e + m + __logf((a0 + a1) + (a2 + a3));
    }

    // logZ = logsumexp over lanes of d
    float m2 = d;
#pragma unroll
    for (int off = 16; off; off >>= 1)
        m2 = fmaxf(m2, __shfl_xor_sync(FULL, m2, off));
    float s = __expf(d - m2);
#pragma unroll
    for (int off = 16; off; off >>= 1)
        s += __shfl_xor_sync(FULL, s, off);
    float logz = m2 + __logf(s);

    // Gold-path score: sum_{l<len} emit[b,l,tags[l]] + sum_{1<=l<len} trans[tags[l-1],tags[l]]
    const int* trow = tags + b * CRF_L;
    float gs = 0.f;
    for (int l = lane; l < len; l += 32) {
        int tg = __ldg(&trow[l]);
        gs += __ldg(&erow[l * CRF_T + tg]);
        if (l >= 1) {
            int tp = __ldg(&trow[l - 1]);
            gs += __ldg(&trans[tp * CRF_T + tg]);
        }
    }
#pragma unroll
    for (int off = 16; off; off >>= 1)
        gs += __shfl_xor_sync(FULL, gs, off);

    if (lane == 0) out[b] = logz - gs;
}

extern "C" void kernel_launch(void* const* d_in, const int* in_sizes, int n_in,
                              void* d_out, int out_size)
{
    const float* emit    = (const float*)d_in[0];   // (B, L, T) f32
    const float* trans   = (const float*)d_in[1];   // (T, T) f32
    const int*   tags    = (const int*)d_in[2];     // (B, L) i32
    const int*   lengths = (const int*)d_in[3];     // (B,) i32
    float*       out     = (float*)d_out;           // (B,) f32

    (void)in_sizes; (void)n_in; (void)out_size;

    // 2048 warps total: 256 threads/block (8 warps), 256 blocks.
    dim3 block(256);
    dim3 grid(CRF_B / 8);
    crf_forward_kernel<<<grid, block>>>(emit, trans, tags, lengths, out);
}

// round 2
// speedup vs baseline: 7.0563x; 7.0563x over previous
#include <cuda_runtime.h>
#include <cuda_bf16.h>
#include <cstdint>

// CRF loss: out[b] = logZ(b) - gold_score(b)
// B=2048, L=512, T=32. One warp (= one block) per batch; lane j owns state j.
// Recurrence in prob space with M = exp(transition):
//   d'[j] = e[j] + m + log( sum_i exp(d[i]-m) * M[i][j] ),  m = d[0] (1 shfl)
// p-vector broadcast via smem (STS + syncwarp + LDS.128 broadcast) instead of 32 SHFLs.
// emit rows staged through smem with cp.async, 8 rows/chunk, double buffered.

#define CRF_B 2048
#define CRF_L 512
#define CRF_T 32
#define CHUNK 8           // emit rows per staged chunk
#define NCHMAX (CRF_L / CHUNK)

__device__ __forceinline__ unsigned smem_u32(const void* p) {
    return (unsigned)__cvta_generic_to_shared(p);
}

__global__ __launch_bounds__(32)
void crf_forward_kernel(const float* __restrict__ emit,      // (B, L, T)
                        const float* __restrict__ trans,     // (T, T)
                        const int*   __restrict__ tags,      // (B, L)
                        const int*   __restrict__ lengths,   // (B,)
                        float*       __restrict__ out)       // (B,)
{
    const unsigned FULL = 0xffffffffu;
    __shared__ __align__(16) float ebuf[2][CHUNK * CRF_T];   // 2 KB staged emit
    __shared__ __align__(16) float pbuf[2][CRF_T];           // parity p buffers

    const int b    = blockIdx.x;
    const int lane = threadIdx.x;
    const int len  = lengths[b];

    // Column of M = exp(transition): Mcol[i] = exp(trans[i][lane]) (coalesced rows).
    float Mcol[CRF_T];
#pragma unroll
    for (int i = 0; i < CRF_T; i++)
        Mcol[i] = __expf(__ldg(&trans[i * CRF_T + lane]));

    const float* erow = emit + (size_t)b * CRF_L * CRF_T;
    const int nch = (len + CHUNK - 1) / CHUNK;   // chunks covering rows [0, len)

    // ---- cp.async chunk prefetch: chunk c = rows [c*8, c*8+8) = 1024B, 2x16B per lane
    auto issue_chunk = [&](int c) {
        if (c < nch) {
            const char* src = (const char*)(erow + c * (CHUNK * CRF_T));
            unsigned dst = smem_u32(&ebuf[c & 1][0]);
            asm volatile("cp.async.cg.shared.global [%0], [%1], 16;\n"
                         :: "r"(dst + lane * 16), "l"(src + lane * 16));
            asm volatile("cp.async.cg.shared.global [%0], [%1], 16;\n"
                         :: "r"(dst + 512 + lane * 16), "l"(src + 512 + lane * 16));
        }
        asm volatile("cp.async.commit_group;\n");
    };

    issue_chunk(0);
    issue_chunk(1);

    float d = 0.f;
    bool first = true;

    for (int c = 0; c < nch; c++) {
        asm volatile("cp.async.wait_group 1;\n" ::: "memory");
        __syncwarp();
        const float*  E  = &ebuf[c & 1][0];
        const float4* P0 = (const float4*)&pbuf[0][0];
        const float4* P1 = (const float4*)&pbuf[1][0];

        if (first) { d = E[lane]; first = false; }   // alpha_0 = emit[b,0,:]

#pragma unroll
        for (int k = 0; k < CHUNK; k++) {
            const int row = c * CHUNK + k;
            if (row >= 1 && row < len) {             // warp-uniform predicate
                float e = E[k * CRF_T + lane];
                float m = __shfl_sync(FULL, d, 0);
                float p = __expf(d - m);
                float em = e + m;                    // off critical path
                const int par = row & 1;
                pbuf[par][lane] = p;
                __syncwarp();
                const float4* P = par ? P1 : P0;
                float a0 = 0.f, a1 = 0.f, a2 = 0.f, a3 = 0.f;
#pragma unroll
                for (int q = 0; q < 8; q++) {
                    float4 pv = P[q];                // LDS.128 broadcast
                    a0 = fmaf(pv.x, Mcol[4 * q + 0], a0);
                    a1 = fmaf(pv.y, Mcol[4 * q + 1], a1);
                    a2 = fmaf(pv.z, Mcol[4 * q + 2], a2);
                    a3 = fmaf(pv.w, Mcol[4 * q + 3], a3);
                }
                float s = (a0 + a1) + (a2 + a3);
                d = fmaf(__log2f(s), 0.6931471805599453f, em);
            }
        }
        issue_chunk(c + 2);                          // overlaps next chunk's compute
    }

    // logZ = logsumexp over lanes of d
    float m2 = d;
#pragma unroll
    for (int off = 16; off; off >>= 1)
        m2 = fmaxf(m2, __shfl_xor_sync(FULL, m2, off));
    float s = __expf(d - m2);
#pragma unroll
    for (int off = 16; off; off >>= 1)
        s += __shfl_xor_sync(FULL, s, off);
    float logz = m2 + __logf(s);

    // Gold-path score
    const int* trow = tags + b * CRF_L;
    float gs = 0.f;
    for (int l = lane; l < len; l += 32) {
        int tg = __ldg(&trow[l]);
        gs += __ldg(&erow[l * CRF_T + tg]);
        if (l >= 1) {
            int tp = __ldg(&trow[l - 1]);
            gs += __ldg(&trans[tp * CRF_T + tg]);
        }
    }
#pragma unroll
    for (int off = 16; off; off >>= 1)
        gs += __shfl_xor_sync(FULL, gs, off);

    if (lane == 0) out[b] = logz - gs;
}

extern "C" void kernel_launch(void* const* d_in, const int* in_sizes, int n_in,
                              void* d_out, int out_size)
{
    const float* emit    = (const float*)d_in[0];
    const float* trans   = (const float*)d_in[1];
    const int*   tags    = (const int*)d_in[2];
    const int*   lengths = (const int*)d_in[3];
    float*       out     = (float*)d_out;

    (void)in_sizes; (void)n_in; (void)out_size;

    crf_forward_kernel<<<CRF_B, 32>>>(emit, trans, tags, lengths, out);
}